// round 1
// baseline (speedup 1.0000x reference)
#include <cuda_runtime.h>

#define BATCH 64
#define SEQ   341
#define DIM   768
#define HEADS 12
#define HD    64
#define MTOT  (BATCH*SEQ)     // 21824
#define QKVC  (3*DIM)         // 2304

// Scratch (allocation-free): qkv [MTOT, 2304], attention output [MTOT, 768]
__device__ float g_qkv[(size_t)MTOT * QKVC];
__device__ float g_attn[(size_t)MTOT * DIM];

// ---------------------------------------------------------------------------
// C[M,Nout] = A[M,K] * W[Nout,K]^T + bias[Nout]
// Both A and W are K-major (row-major with K contiguous). 128x128x8 tiles,
// 256 threads, 8x8 microtile per thread (split 4+4 to keep float4 smem reads).
// Nout must be a multiple of 128 (2304 and 768 both are); M edge is guarded.
// ---------------------------------------------------------------------------
__global__ __launch_bounds__(256) void sgemm_nt_bias(
    const float* __restrict__ A, const float* __restrict__ W,
    const float* __restrict__ bias, float* __restrict__ C,
    int M, int Nout, int K)
{
    __shared__ float As[8][128];
    __shared__ float Ws[8][128];
    const int tid = threadIdx.x;
    const int m0 = blockIdx.y * 128;
    const int n0 = blockIdx.x * 128;
    const int tR = tid >> 4;        // 0..15
    const int tC = tid & 15;        // 0..15
    const int lr = tid >> 1;        // 0..127 load row
    const int lc = (tid & 1) << 2;  // 0 or 4

    const bool aval = (m0 + lr) < M;
    const float* Aptr = A + (size_t)(m0 + lr) * K + lc;
    const float* Wptr = W + (size_t)(n0 + lr) * K + lc;

    float acc[8][8];
#pragma unroll
    for (int i = 0; i < 8; i++)
#pragma unroll
        for (int j = 0; j < 8; j++) acc[i][j] = 0.f;

    for (int k0 = 0; k0 < K; k0 += 8) {
        float4 av = aval ? *(const float4*)(Aptr + k0) : make_float4(0.f, 0.f, 0.f, 0.f);
        float4 wv = *(const float4*)(Wptr + k0);
        __syncthreads();
        As[lc + 0][lr] = av.x; As[lc + 1][lr] = av.y; As[lc + 2][lr] = av.z; As[lc + 3][lr] = av.w;
        Ws[lc + 0][lr] = wv.x; Ws[lc + 1][lr] = wv.y; Ws[lc + 2][lr] = wv.z; Ws[lc + 3][lr] = wv.w;
        __syncthreads();
#pragma unroll
        for (int kk = 0; kk < 8; kk++) {
            float4 a0 = *(const float4*)&As[kk][tR * 4];
            float4 a1 = *(const float4*)&As[kk][64 + tR * 4];
            float4 b0 = *(const float4*)&Ws[kk][tC * 4];
            float4 b1 = *(const float4*)&Ws[kk][64 + tC * 4];
            float a[8] = {a0.x, a0.y, a0.z, a0.w, a1.x, a1.y, a1.z, a1.w};
            float b[8] = {b0.x, b0.y, b0.z, b0.w, b1.x, b1.y, b1.z, b1.w};
#pragma unroll
            for (int i = 0; i < 8; i++)
#pragma unroll
                for (int j = 0; j < 8; j++)
                    acc[i][j] = fmaf(a[i], b[j], acc[i][j]);
        }
    }

#pragma unroll
    for (int i = 0; i < 8; i++) {
        int m = m0 + ((i < 4) ? (tR * 4 + i) : (64 + tR * 4 + i - 4));
        if (m >= M) continue;
#pragma unroll
        for (int jh = 0; jh < 2; jh++) {
            int n = n0 + jh * 64 + tC * 4;
            float4 o;
            o.x = acc[i][jh * 4 + 0] + bias[n + 0];
            o.y = acc[i][jh * 4 + 1] + bias[n + 1];
            o.z = acc[i][jh * 4 + 2] + bias[n + 2];
            o.w = acc[i][jh * 4 + 3] + bias[n + 3];
            *(float4*)&C[(size_t)m * Nout + n] = o;
        }
    }
}

// ---------------------------------------------------------------------------
// Flash attention with scale-causal mask.
// One block per (q-tile of 64, b*H+h). 256 threads = 16x16; each thread owns
// a 4(q) x 4(k or d) microtile. Online softmax across the 6 key tiles.
// Mask: key kg allowed iff kg < limit(qg), with
//   limit(q) = 341 (q==0 or q>=85), 5 (q in [1,5)), 21 ([5,21)), 85 ([21,85)).
// P is stored in smem with per-row rotation col' = (k + 4q) & 63 to avoid
// stride-64 bank conflicts in the P@V phase.
// ---------------------------------------------------------------------------
__global__ __launch_bounds__(256) void attn_kernel(
    const float* __restrict__ qkv, float* __restrict__ op)
{
    __shared__ float Qs[64][64];  // [d][q]   (Q transposed)
    __shared__ float KP[64][64];  // phase1: K^T [d][k]; phase2: P swizzled
    __shared__ float Vs[64][64];  // [k][d]

    const int qt = blockIdx.x;        // 0..5
    const int bh = blockIdx.y;        // 0..767
    const int b = bh / HEADS, h = bh - b * HEADS;
    const int tid = threadIdx.x;
    const int tx = tid & 15, ty = tid >> 4;
    const int q0 = qt * 64;
    const float* base = qkv + (size_t)b * SEQ * QKVC + h * HD;

    for (int i = tid; i < 4096; i += 256) {
        int row = i >> 6, d = i & 63;
        int qg = q0 + row;
        Qs[d][row] = (qg < SEQ) ? base[(size_t)qg * QKVC + d] : 0.f;
    }

    float m_i[4], l_i[4], O[4][4];
#pragma unroll
    for (int i = 0; i < 4; i++) {
        m_i[i] = -1e30f; l_i[i] = 0.f;
#pragma unroll
        for (int j = 0; j < 4; j++) O[i][j] = 0.f;
    }

    int limit[4];
#pragma unroll
    for (int i = 0; i < 4; i++) {
        int qg = q0 + ty * 4 + i;
        limit[i] = (qg == 0 || qg >= 85) ? SEQ : (qg < 5 ? 5 : (qg < 21 ? 21 : 85));
    }

    for (int kt = 0; kt < 6; kt++) {
        const int k0 = kt * 64;
        __syncthreads();  // previous tile's P/V reads complete
        for (int i = tid; i < 4096; i += 256) {
            int row = i >> 6, d = i & 63;
            int kg = k0 + row;
            float kv = 0.f, vv = 0.f;
            if (kg < SEQ) {
                kv = base[(size_t)kg * QKVC + DIM + d];
                vv = base[(size_t)kg * QKVC + 2 * DIM + d];
            }
            KP[d][row] = kv;
            Vs[row][d] = vv;
        }
        __syncthreads();

        // S = Q * K^T
        float S[4][4];
#pragma unroll
        for (int i = 0; i < 4; i++)
#pragma unroll
            for (int j = 0; j < 4; j++) S[i][j] = 0.f;

#pragma unroll 8
        for (int kk = 0; kk < 64; kk++) {
            float4 a4 = *(const float4*)&Qs[kk][ty * 4];
            float4 b4 = *(const float4*)&KP[kk][tx * 4];
            float a[4] = {a4.x, a4.y, a4.z, a4.w};
            float bv[4] = {b4.x, b4.y, b4.z, b4.w};
#pragma unroll
            for (int i = 0; i < 4; i++)
#pragma unroll
                for (int j = 0; j < 4; j++)
                    S[i][j] = fmaf(a[i], bv[j], S[i][j]);
        }

        // scale + mask + row max
        float mnew[4];
#pragma unroll
        for (int i = 0; i < 4; i++) {
            float mm = -1e30f;
#pragma unroll
            for (int j = 0; j < 4; j++) {
                int kg = k0 + tx * 4 + j;
                S[i][j] = (kg < limit[i]) ? S[i][j] * 0.125f : -1e30f;
                mm = fmaxf(mm, S[i][j]);
            }
            mnew[i] = mm;
        }
#pragma unroll
        for (int sh = 8; sh; sh >>= 1)
#pragma unroll
            for (int i = 0; i < 4; i++)
                mnew[i] = fmaxf(mnew[i], __shfl_xor_sync(0xffffffffu, mnew[i], sh));

        // online softmax update
        float alpha[4], rs[4];
#pragma unroll
        for (int i = 0; i < 4; i++) {
            float m2 = fmaxf(m_i[i], mnew[i]);
            alpha[i] = __expf(m_i[i] - m2);
            m_i[i] = m2;
            float r = 0.f;
#pragma unroll
            for (int j = 0; j < 4; j++) { S[i][j] = __expf(S[i][j] - m2); r += S[i][j]; }
            rs[i] = r;
        }
#pragma unroll
        for (int sh = 8; sh; sh >>= 1)
#pragma unroll
            for (int i = 0; i < 4; i++)
                rs[i] += __shfl_xor_sync(0xffffffffu, rs[i], sh);
#pragma unroll
        for (int i = 0; i < 4; i++) {
            l_i[i] = l_i[i] * alpha[i] + rs[i];
#pragma unroll
            for (int j = 0; j < 4; j++) O[i][j] *= alpha[i];
        }

        // P -> smem (swizzled), reusing K buffer
        __syncthreads();
#pragma unroll
        for (int i = 0; i < 4; i++) {
            int q = ty * 4 + i;
            int c = (tx * 4 + q * 4) & 63;
            *(float4*)&KP[q][c] = make_float4(S[i][0], S[i][1], S[i][2], S[i][3]);
        }
        __syncthreads();

        // O += P @ V
#pragma unroll 4
        for (int kc = 0; kc < 16; kc++) {
            float4 v0 = *(const float4*)&Vs[kc * 4 + 0][tx * 4];
            float4 v1 = *(const float4*)&Vs[kc * 4 + 1][tx * 4];
            float4 v2 = *(const float4*)&Vs[kc * 4 + 2][tx * 4];
            float4 v3 = *(const float4*)&Vs[kc * 4 + 3][tx * 4];
#pragma unroll
            for (int i = 0; i < 4; i++) {
                int q = ty * 4 + i;
                float4 p = *(const float4*)&KP[q][((kc + q) & 15) * 4];
                O[i][0] = fmaf(p.x, v0.x, fmaf(p.y, v1.x, fmaf(p.z, v2.x, fmaf(p.w, v3.x, O[i][0]))));
                O[i][1] = fmaf(p.x, v0.y, fmaf(p.y, v1.y, fmaf(p.z, v2.y, fmaf(p.w, v3.y, O[i][1]))));
                O[i][2] = fmaf(p.x, v0.z, fmaf(p.y, v1.z, fmaf(p.z, v2.z, fmaf(p.w, v3.z, O[i][2]))));
                O[i][3] = fmaf(p.x, v0.w, fmaf(p.y, v1.w, fmaf(p.z, v2.w, fmaf(p.w, v3.w, O[i][3]))));
            }
        }
    }

    // normalize + store to [b, n, h*64 + d]
#pragma unroll
    for (int i = 0; i < 4; i++) {
        int qg = q0 + ty * 4 + i;
        if (qg >= SEQ) continue;
        float inv = 1.f / l_i[i];
        float4 o = make_float4(O[i][0] * inv, O[i][1] * inv, O[i][2] * inv, O[i][3] * inv);
        *(float4*)&op[(size_t)(b * SEQ + qg) * DIM + h * HD + tx * 4] = o;
    }
}

extern "C" void kernel_launch(void* const* d_in, const int* in_sizes, int n_in,
                              void* d_out, int out_size) {
    const float* x      = (const float*)d_in[0];
    const float* qkv_w  = (const float*)d_in[1];
    const float* qkv_b  = (const float*)d_in[2];
    const float* proj_w = (const float*)d_in[3];
    const float* proj_b = (const float*)d_in[4];
    float* out = (float*)d_out;

    float* qkvp = nullptr;
    float* attnp = nullptr;
    cudaGetSymbolAddress((void**)&qkvp, g_qkv);
    cudaGetSymbolAddress((void**)&attnp, g_attn);

    dim3 blk(256);
    dim3 g1(QKVC / 128, (MTOT + 127) / 128);
    sgemm_nt_bias<<<g1, blk>>>(x, qkv_w, qkv_b, qkvp, MTOT, QKVC, DIM);

    dim3 g2(6, BATCH * HEADS);
    attn_kernel<<<g2, blk>>>(qkvp, attnp);

    dim3 g3(DIM / 128, (MTOT + 127) / 128);
    sgemm_nt_bias<<<g3, blk>>>(attnp, proj_w, proj_b, out, MTOT, DIM, DIM);
}

// round 2
// speedup vs baseline: 1.4485x; 1.4485x over previous
#include <cuda_runtime.h>

#define BATCH 64
#define SEQ   341
#define DIM   768
#define HEADS 12
#define HD    64
#define MTOT  (BATCH*SEQ)     // 21824
#define QKVC  (3*DIM)         // 2304

// Scratch (allocation-free): qkv [MTOT, 2304], attention output [MTOT, 768]
__device__ float g_qkv[(size_t)MTOT * QKVC];
__device__ float g_attn[(size_t)MTOT * DIM];

__device__ __forceinline__ unsigned f2tf(float f) {
    unsigned u;
    asm("cvt.rna.tf32.f32 %0, %1;" : "=r"(u) : "f"(f));
    return u;
}

// ---------------------------------------------------------------------------
// C[M,Nout] = A[M,K] * W[Nout,K]^T + bias[Nout]  via tf32 mma.sync.m16n8k8.
// 128x128x32 tiles, 256 threads = 8 warps (4 along M x 2 along N),
// warp tile 32x64 = 2 m-frags x 8 n-frags. smem row stride 36 (bank-bijective
// fragment loads). Nout must be a multiple of 128; M edge guarded.
// ---------------------------------------------------------------------------
#define PADK 36
__global__ __launch_bounds__(256) void gemm_tf32(
    const float* __restrict__ A, const float* __restrict__ W,
    const float* __restrict__ bias, float* __restrict__ C,
    int M, int Nout, int K)
{
    __shared__ unsigned As[128 * PADK];
    __shared__ unsigned Ws[128 * PADK];

    const int tid = threadIdx.x;
    const int wid = tid >> 5, lane = tid & 31;
    const int g = lane >> 2, c = lane & 3;
    const int wm = (wid & 3) * 32, wn = (wid >> 2) * 64;
    const int m0 = blockIdx.y * 128, n0 = blockIdx.x * 128;

    const int lm = tid >> 3;          // 0..31 (row within 32-row pass)
    const int lk = (tid & 7) << 2;    // 0,4,...,28

    float acc[2][8][4];
#pragma unroll
    for (int mi = 0; mi < 2; mi++)
#pragma unroll
        for (int nf = 0; nf < 8; nf++)
#pragma unroll
            for (int t = 0; t < 4; t++) acc[mi][nf][t] = 0.f;

    for (int k0 = 0; k0 < K; k0 += 32) {
        // global -> smem (with tf32 conversion)
#pragma unroll
        for (int p = 0; p < 4; p++) {
            int row = lm + p * 32;
            int m = m0 + row;
            float4 av = (m < M) ? *(const float4*)&A[(size_t)m * K + k0 + lk]
                                : make_float4(0.f, 0.f, 0.f, 0.f);
            unsigned* sa = &As[row * PADK + lk];
            sa[0] = f2tf(av.x); sa[1] = f2tf(av.y); sa[2] = f2tf(av.z); sa[3] = f2tf(av.w);
            int n = n0 + row;
            float4 wv = *(const float4*)&W[(size_t)n * K + k0 + lk];
            unsigned* sw = &Ws[row * PADK + lk];
            sw[0] = f2tf(wv.x); sw[1] = f2tf(wv.y); sw[2] = f2tf(wv.z); sw[3] = f2tf(wv.w);
        }
        __syncthreads();

#pragma unroll
        for (int kk = 0; kk < 4; kk++) {
            const int kb = kk * 8;
            unsigned a0[2], a1[2], a2[2], a3[2];
#pragma unroll
            for (int mi = 0; mi < 2; mi++) {
                int r = (wm + mi * 16 + g) * PADK + kb + c;
                a0[mi] = As[r];
                a1[mi] = As[r + 8 * PADK];
                a2[mi] = As[r + 4];
                a3[mi] = As[r + 8 * PADK + 4];
            }
            unsigned b0[8], b1[8];
#pragma unroll
            for (int nf = 0; nf < 8; nf++) {
                int r = (wn + nf * 8 + g) * PADK + kb + c;
                b0[nf] = Ws[r];
                b1[nf] = Ws[r + 4];
            }
#pragma unroll
            for (int mi = 0; mi < 2; mi++)
#pragma unroll
                for (int nf = 0; nf < 8; nf++) {
                    float* d = acc[mi][nf];
                    asm volatile(
                        "mma.sync.aligned.m16n8k8.row.col.f32.tf32.tf32.f32 "
                        "{%0,%1,%2,%3}, {%4,%5,%6,%7}, {%8,%9}, {%0,%1,%2,%3};"
                        : "+f"(d[0]), "+f"(d[1]), "+f"(d[2]), "+f"(d[3])
                        : "r"(a0[mi]), "r"(a1[mi]), "r"(a2[mi]), "r"(a3[mi]),
                          "r"(b0[nf]), "r"(b1[nf]));
                }
        }
        __syncthreads();
    }

    // epilogue: add bias, store float2 pairs
#pragma unroll
    for (int mi = 0; mi < 2; mi++) {
        int row0 = m0 + wm + mi * 16 + g;
        int row1 = row0 + 8;
#pragma unroll
        for (int nf = 0; nf < 8; nf++) {
            int n = n0 + wn + nf * 8 + 2 * c;
            float2 bv = *(const float2*)&bias[n];
            if (row0 < M) {
                float2 o = make_float2(acc[mi][nf][0] + bv.x, acc[mi][nf][1] + bv.y);
                *(float2*)&C[(size_t)row0 * Nout + n] = o;
            }
            if (row1 < M) {
                float2 o = make_float2(acc[mi][nf][2] + bv.x, acc[mi][nf][3] + bv.y);
                *(float2*)&C[(size_t)row1 * Nout + n] = o;
            }
        }
    }
}

// ---------------------------------------------------------------------------
// Flash attention with scale-causal mask (fp32 FMA; tf32-mma is Round 3).
// One block per (q-tile of 64, b*H+h). 256 threads = 16x16; each thread owns
// a 4(q) x 4(k or d) microtile. Online softmax across the 6 key tiles.
// Mask: key kg allowed iff kg < limit(qg), with
//   limit(q) = 341 (q==0 or q>=85), 5 (q in [1,5)), 21 ([5,21)), 85 ([21,85)).
// ---------------------------------------------------------------------------
__global__ __launch_bounds__(256) void attn_kernel(
    const float* __restrict__ qkv, float* __restrict__ op)
{
    __shared__ float Qs[64][64];  // [d][q]   (Q transposed)
    __shared__ float KP[64][64];  // phase1: K^T [d][k]; phase2: P swizzled
    __shared__ float Vs[64][64];  // [k][d]

    const int qt = blockIdx.x;        // 0..5
    const int bh = blockIdx.y;        // 0..767
    const int b = bh / HEADS, h = bh - b * HEADS;
    const int tid = threadIdx.x;
    const int tx = tid & 15, ty = tid >> 4;
    const int q0 = qt * 64;
    const float* base = qkv + (size_t)b * SEQ * QKVC + h * HD;

    for (int i = tid; i < 4096; i += 256) {
        int row = i >> 6, d = i & 63;
        int qg = q0 + row;
        Qs[d][row] = (qg < SEQ) ? base[(size_t)qg * QKVC + d] : 0.f;
    }

    float m_i[4], l_i[4], O[4][4];
#pragma unroll
    for (int i = 0; i < 4; i++) {
        m_i[i] = -1e30f; l_i[i] = 0.f;
#pragma unroll
        for (int j = 0; j < 4; j++) O[i][j] = 0.f;
    }

    int limit[4];
#pragma unroll
    for (int i = 0; i < 4; i++) {
        int qg = q0 + ty * 4 + i;
        limit[i] = (qg == 0 || qg >= 85) ? SEQ : (qg < 5 ? 5 : (qg < 21 ? 21 : 85));
    }

    for (int kt = 0; kt < 6; kt++) {
        const int k0 = kt * 64;
        __syncthreads();  // previous tile's P/V reads complete
        for (int i = tid; i < 4096; i += 256) {
            int row = i >> 6, d = i & 63;
            int kg = k0 + row;
            float kv = 0.f, vv = 0.f;
            if (kg < SEQ) {
                kv = base[(size_t)kg * QKVC + DIM + d];
                vv = base[(size_t)kg * QKVC + 2 * DIM + d];
            }
            KP[d][row] = kv;
            Vs[row][d] = vv;
        }
        __syncthreads();

        // S = Q * K^T
        float S[4][4];
#pragma unroll
        for (int i = 0; i < 4; i++)
#pragma unroll
            for (int j = 0; j < 4; j++) S[i][j] = 0.f;

#pragma unroll 8
        for (int kk = 0; kk < 64; kk++) {
            float4 a4 = *(const float4*)&Qs[kk][ty * 4];
            float4 b4 = *(const float4*)&KP[kk][tx * 4];
            float a[4] = {a4.x, a4.y, a4.z, a4.w};
            float bv[4] = {b4.x, b4.y, b4.z, b4.w};
#pragma unroll
            for (int i = 0; i < 4; i++)
#pragma unroll
                for (int j = 0; j < 4; j++)
                    S[i][j] = fmaf(a[i], bv[j], S[i][j]);
        }

        // scale + mask + row max
        float mnew[4];
#pragma unroll
        for (int i = 0; i < 4; i++) {
            float mm = -1e30f;
#pragma unroll
            for (int j = 0; j < 4; j++) {
                int kg = k0 + tx * 4 + j;
                S[i][j] = (kg < limit[i]) ? S[i][j] * 0.125f : -1e30f;
                mm = fmaxf(mm, S[i][j]);
            }
            mnew[i] = mm;
        }
#pragma unroll
        for (int sh = 8; sh; sh >>= 1)
#pragma unroll
            for (int i = 0; i < 4; i++)
                mnew[i] = fmaxf(mnew[i], __shfl_xor_sync(0xffffffffu, mnew[i], sh));

        // online softmax update
        float alpha[4], rs[4];
#pragma unroll
        for (int i = 0; i < 4; i++) {
            float m2 = fmaxf(m_i[i], mnew[i]);
            alpha[i] = __expf(m_i[i] - m2);
            m_i[i] = m2;
            float r = 0.f;
#pragma unroll
            for (int j = 0; j < 4; j++) { S[i][j] = __expf(S[i][j] - m2); r += S[i][j]; }
            rs[i] = r;
        }
#pragma unroll
        for (int sh = 8; sh; sh >>= 1)
#pragma unroll
            for (int i = 0; i < 4; i++)
                rs[i] += __shfl_xor_sync(0xffffffffu, rs[i], sh);
#pragma unroll
        for (int i = 0; i < 4; i++) {
            l_i[i] = l_i[i] * alpha[i] + rs[i];
#pragma unroll
            for (int j = 0; j < 4; j++) O[i][j] *= alpha[i];
        }

        // P -> smem (swizzled), reusing K buffer
        __syncthreads();
#pragma unroll
        for (int i = 0; i < 4; i++) {
            int q = ty * 4 + i;
            int cswz = (tx * 4 + q * 4) & 63;
            *(float4*)&KP[q][cswz] = make_float4(S[i][0], S[i][1], S[i][2], S[i][3]);
        }
        __syncthreads();

        // O += P @ V
#pragma unroll 4
        for (int kc = 0; kc < 16; kc++) {
            float4 v0 = *(const float4*)&Vs[kc * 4 + 0][tx * 4];
            float4 v1 = *(const float4*)&Vs[kc * 4 + 1][tx * 4];
            float4 v2 = *(const float4*)&Vs[kc * 4 + 2][tx * 4];
            float4 v3 = *(const float4*)&Vs[kc * 4 + 3][tx * 4];
#pragma unroll
            for (int i = 0; i < 4; i++) {
                int q = ty * 4 + i;
                float4 p = *(const float4*)&KP[q][((kc + q) & 15) * 4];
                O[i][0] = fmaf(p.x, v0.x, fmaf(p.y, v1.x, fmaf(p.z, v2.x, fmaf(p.w, v3.x, O[i][0]))));
                O[i][1] = fmaf(p.x, v0.y, fmaf(p.y, v1.y, fmaf(p.z, v2.y, fmaf(p.w, v3.y, O[i][1]))));
                O[i][2] = fmaf(p.x, v0.z, fmaf(p.y, v1.z, fmaf(p.z, v2.z, fmaf(p.w, v3.z, O[i][2]))));
                O[i][3] = fmaf(p.x, v0.w, fmaf(p.y, v1.w, fmaf(p.z, v2.w, fmaf(p.w, v3.w, O[i][3]))));
            }
        }
    }

    // normalize + store to [b, n, h*64 + d]
#pragma unroll
    for (int i = 0; i < 4; i++) {
        int qg = q0 + ty * 4 + i;
        if (qg >= SEQ) continue;
        float inv = 1.f / l_i[i];
        float4 o = make_float4(O[i][0] * inv, O[i][1] * inv, O[i][2] * inv, O[i][3] * inv);
        *(float4*)&op[(size_t)(b * SEQ + qg) * DIM + h * HD + tx * 4] = o;
    }
}

extern "C" void kernel_launch(void* const* d_in, const int* in_sizes, int n_in,
                              void* d_out, int out_size) {
    const float* x      = (const float*)d_in[0];
    const float* qkv_w  = (const float*)d_in[1];
    const float* qkv_b  = (const float*)d_in[2];
    const float* proj_w = (const float*)d_in[3];
    const float* proj_b = (const float*)d_in[4];
    float* out = (float*)d_out;

    float* qkvp = nullptr;
    float* attnp = nullptr;
    cudaGetSymbolAddress((void**)&qkvp, g_qkv);
    cudaGetSymbolAddress((void**)&attnp, g_attn);

    dim3 blk(256);
    dim3 g1(QKVC / 128, (MTOT + 127) / 128);
    gemm_tf32<<<g1, blk>>>(x, qkv_w, qkv_b, qkvp, MTOT, QKVC, DIM);

    dim3 g2(6, BATCH * HEADS);
    attn_kernel<<<g2, blk>>>(qkvp, attnp);

    dim3 g3(DIM / 128, (MTOT + 127) / 128);
    gemm_tf32<<<g3, blk>>>(attnp, proj_w, proj_b, out, MTOT, DIM, DIM);
}

// round 3
// speedup vs baseline: 2.8774x; 1.9864x over previous
#include <cuda_runtime.h>

#define BATCH 64
#define SEQ   341
#define DIM   768
#define HEADS 12
#define HD    64
#define MTOT  (BATCH*SEQ)     // 21824
#define QKVC  (3*DIM)         // 2304

// Scratch (allocation-free): qkv [MTOT, 2304], attention output [MTOT, 768]
__device__ float g_qkv[(size_t)MTOT * QKVC];
__device__ float g_attn[(size_t)MTOT * DIM];

__device__ __forceinline__ unsigned f2tf(float f) {
    unsigned u;
    asm("cvt.rna.tf32.f32 %0, %1;" : "=r"(u) : "f"(f));
    return u;
}
__device__ __forceinline__ unsigned sptr(const void* p) {
    return (unsigned)__cvta_generic_to_shared(p);
}
__device__ __forceinline__ void mma8(float* d, const unsigned* a, unsigned b0, unsigned b1) {
    asm volatile(
        "mma.sync.aligned.m16n8k8.row.col.f32.tf32.tf32.f32 "
        "{%0,%1,%2,%3}, {%4,%5,%6,%7}, {%8,%9}, {%0,%1,%2,%3};"
        : "+f"(d[0]), "+f"(d[1]), "+f"(d[2]), "+f"(d[3])
        : "r"(a[0]), "r"(a[1]), "r"(a[2]), "r"(a[3]), "r"(b0), "r"(b1));
}

// ---------------------------------------------------------------------------
// C[M,Nout] = A[M,K] * W[Nout,K]^T + bias[Nout], tf32 mma, 3-stage cp.async.
// 128x128x16 tiles, 256 threads = 8 warps (4 along M x 2 along N).
// fp32 stored in smem (row stride 20 -> bank-bijective fragment loads),
// cvt.rna.tf32 applied at fragment load time.
// ---------------------------------------------------------------------------
#define PAD 20
#define SSZ (128 * PAD)
__global__ __launch_bounds__(256) void gemm_tf32(
    const float* __restrict__ A, const float* __restrict__ W,
    const float* __restrict__ bias, float* __restrict__ C,
    int M, int Nout, int K)
{
    extern __shared__ float sm[];
    float* As = sm;             // 3 stages
    float* Ws = sm + 3 * SSZ;   // 3 stages

    const int tid = threadIdx.x;
    const int wid = tid >> 5, lane = tid & 31;
    const int g = lane >> 2, c = lane & 3;
    const int wm = (wid & 3) * 32, wn = (wid >> 2) * 64;
    const int m0 = blockIdx.y * 128, n0 = blockIdx.x * 128;

    const int lrow = tid >> 2;          // 0..63
    const int lcol = (tid & 3) << 2;    // 0,4,8,12

    float acc[2][8][4];
#pragma unroll
    for (int mi = 0; mi < 2; mi++)
#pragma unroll
        for (int nf = 0; nf < 8; nf++)
#pragma unroll
            for (int t = 0; t < 4; t++) acc[mi][nf][t] = 0.f;

    const int niter = K >> 4;

#define ISSUE(it, s)                                                          \
    {                                                                         \
        int _k0 = (it) << 4;                                                  \
        _Pragma("unroll")                                                     \
        for (int p = 0; p < 2; p++) {                                         \
            int row = lrow + p * 64;                                          \
            int m = m0 + row;                                                 \
            unsigned da = sptr(&As[(s) * SSZ + row * PAD + lcol]);            \
            const float* ga = A + (size_t)(m < M ? m : 0) * K + _k0 + lcol;   \
            int szv = (m < M) ? 16 : 0;                                       \
            asm volatile("cp.async.ca.shared.global [%0],[%1],16,%2;"         \
                         :: "r"(da), "l"(ga), "r"(szv));                      \
            unsigned dw = sptr(&Ws[(s) * SSZ + row * PAD + lcol]);            \
            const float* gw = W + (size_t)(n0 + row) * K + _k0 + lcol;        \
            asm volatile("cp.async.ca.shared.global [%0],[%1],16;"            \
                         :: "r"(dw), "l"(gw));                                \
        }                                                                     \
    }

    ISSUE(0, 0); asm volatile("cp.async.commit_group;");
    ISSUE(1, 1); asm volatile("cp.async.commit_group;");

    int buf = 0;
    for (int it = 0; it < niter; ++it) {
        asm volatile("cp.async.wait_group 1;");
        __syncthreads();
        if (it + 2 < niter) {
            int s = (buf + 2 >= 3) ? buf - 1 : buf + 2;
            ISSUE(it + 2, s);
        }
        asm volatile("cp.async.commit_group;");

        const float* Ab = As + buf * SSZ;
        const float* Wb = Ws + buf * SSZ;
#pragma unroll
        for (int ks = 0; ks < 2; ks++) {
            const int kb = ks * 8;
            unsigned a[2][4];
#pragma unroll
            for (int mi = 0; mi < 2; mi++) {
                int base = (wm + mi * 16 + g) * PAD + kb + c;
                a[mi][0] = f2tf(Ab[base]);
                a[mi][1] = f2tf(Ab[base + 8 * PAD]);
                a[mi][2] = f2tf(Ab[base + 4]);
                a[mi][3] = f2tf(Ab[base + 8 * PAD + 4]);
            }
#pragma unroll
            for (int nf = 0; nf < 8; nf++) {
                int bb = (wn + nf * 8 + g) * PAD + kb + c;
                unsigned b0 = f2tf(Wb[bb]);
                unsigned b1 = f2tf(Wb[bb + 4]);
                mma8(acc[0][nf], a[0], b0, b1);
                mma8(acc[1][nf], a[1], b0, b1);
            }
        }
        buf = (buf + 1 == 3) ? 0 : buf + 1;
    }

    // epilogue: add bias, store float2 pairs
#pragma unroll
    for (int mi = 0; mi < 2; mi++) {
        int row0 = m0 + wm + mi * 16 + g;
        int row1 = row0 + 8;
#pragma unroll
        for (int nf = 0; nf < 8; nf++) {
            int n = n0 + wn + nf * 8 + 2 * c;
            float2 bv = *(const float2*)&bias[n];
            if (row0 < M) {
                float2 o = make_float2(acc[mi][nf][0] + bv.x, acc[mi][nf][1] + bv.y);
                *(float2*)&C[(size_t)row0 * Nout + n] = o;
            }
            if (row1 < M) {
                float2 o = make_float2(acc[mi][nf][2] + bv.x, acc[mi][nf][3] + bv.y);
                *(float2*)&C[(size_t)row1 * Nout + n] = o;
            }
        }
    }
#undef ISSUE
}

// ---------------------------------------------------------------------------
// Flash attention, tf32 mma. One block per (q-tile 64, b*H+h), 128 threads
// = 4 warps, warp w owns q rows [16w, 16w+16). Online softmax on fragments.
// Mask: key allowed iff key < limit(q);
//   limit(q) = 341 (q==0 or q>=85), 5 (q<5), 21 (q<21), 85 (q<85).
// smem strides: Q/K/P 68 (banks 4g+c bijective), V 72 (banks 8c+g bijective).
// ---------------------------------------------------------------------------
#define QST 68
#define VST 72
__global__ __launch_bounds__(128) void attn_mma(
    const float* __restrict__ qkv, float* __restrict__ op)
{
    extern __shared__ float sm[];
    float* Qs  = sm;                  // [64][68]
    float* KPs = sm + 64 * QST;       // [64][68]  K tile, then P
    float* Vs  = sm + 2 * 64 * QST;   // [64][72]

    const int qt = blockIdx.x;
    const int bh = blockIdx.y;
    const int b = bh / HEADS, h = bh - b * HEADS;
    const int tid = threadIdx.x;
    const int wid = tid >> 5, lane = tid & 31;
    const int g = lane >> 2, c = lane & 3;
    const int wq = wid * 16;
    const int q0 = qt * 64;
    const float* base = qkv + (size_t)b * SEQ * QKVC + h * HD;

    // load Q tile (scaled by softmax scale 1/8)
    for (int idx = tid; idx < 1024; idx += 128) {
        int row = idx >> 4, c4 = (idx & 15) << 2;
        int qg = q0 + row;
        float4 v = make_float4(0.f, 0.f, 0.f, 0.f);
        if (qg < SEQ) v = *(const float4*)&base[(size_t)qg * QKVC + c4];
        float* d = &Qs[row * QST + c4];
        d[0] = v.x * 0.125f; d[1] = v.y * 0.125f; d[2] = v.z * 0.125f; d[3] = v.w * 0.125f;
    }

    const int row0 = q0 + wq + g;
    const int row1 = row0 + 8;
    const int limit0 = (row0 == 0 || row0 >= 85) ? SEQ : (row0 < 5 ? 5 : (row0 < 21 ? 21 : 85));
    const int limit1 = (row1 == 0 || row1 >= 85) ? SEQ : (row1 < 5 ? 5 : (row1 < 21 ? 21 : 85));

    float m0 = -1e30f, m1 = -1e30f, l0 = 0.f, l1 = 0.f;
    float O[8][4];
#pragma unroll
    for (int nf = 0; nf < 8; nf++)
#pragma unroll
        for (int t = 0; t < 4; t++) O[nf][t] = 0.f;

    for (int kt = 0; kt < 6; kt++) {
        const int k0 = kt * 64;
        __syncthreads();  // prior-tile P/V reads and Q load complete
        for (int idx = tid; idx < 1024; idx += 128) {
            int row = idx >> 4, c4 = (idx & 15) << 2;
            int kg = k0 + row;
            float4 kv = make_float4(0.f, 0.f, 0.f, 0.f);
            float4 vv = make_float4(0.f, 0.f, 0.f, 0.f);
            if (kg < SEQ) {
                kv = *(const float4*)&base[(size_t)kg * QKVC + DIM + c4];
                vv = *(const float4*)&base[(size_t)kg * QKVC + 2 * DIM + c4];
            }
            *(float4*)&KPs[row * QST + c4] = kv;   // QST=68: float4 aligned (68%4==0)
            float* vd = &Vs[row * VST + c4];
            vd[0] = vv.x; vd[1] = vv.y; vd[2] = vv.z; vd[3] = vv.w;
        }
        __syncthreads();

        // S = Q*K^T (warp computes its 16x64 stripe)
        float S[8][4];
#pragma unroll
        for (int nf = 0; nf < 8; nf++)
#pragma unroll
            for (int t = 0; t < 4; t++) S[nf][t] = 0.f;

#pragma unroll
        for (int ks = 0; ks < 8; ks++) {
            const int kb = ks * 8;
            unsigned a[4];
            int ab = (wq + g) * QST + kb + c;
            a[0] = f2tf(Qs[ab]);
            a[1] = f2tf(Qs[ab + 8 * QST]);
            a[2] = f2tf(Qs[ab + 4]);
            a[3] = f2tf(Qs[ab + 8 * QST + 4]);
#pragma unroll
            for (int nf = 0; nf < 8; nf++) {
                int bb = (nf * 8 + g) * QST + kb + c;
                unsigned b0 = f2tf(KPs[bb]);
                unsigned b1 = f2tf(KPs[bb + 4]);
                mma8(S[nf], a, b0, b1);
            }
        }

        // mask + row max
        float mx0 = -1e30f, mx1 = -1e30f;
#pragma unroll
        for (int nf = 0; nf < 8; nf++) {
            int key0 = k0 + nf * 8 + 2 * c;
            int key1 = key0 + 1;
            S[nf][0] = (key0 < limit0) ? S[nf][0] : -1e30f;
            S[nf][1] = (key1 < limit0) ? S[nf][1] : -1e30f;
            S[nf][2] = (key0 < limit1) ? S[nf][2] : -1e30f;
            S[nf][3] = (key1 < limit1) ? S[nf][3] : -1e30f;
            mx0 = fmaxf(mx0, fmaxf(S[nf][0], S[nf][1]));
            mx1 = fmaxf(mx1, fmaxf(S[nf][2], S[nf][3]));
        }
        mx0 = fmaxf(mx0, __shfl_xor_sync(0xffffffffu, mx0, 1));
        mx0 = fmaxf(mx0, __shfl_xor_sync(0xffffffffu, mx0, 2));
        mx1 = fmaxf(mx1, __shfl_xor_sync(0xffffffffu, mx1, 1));
        mx1 = fmaxf(mx1, __shfl_xor_sync(0xffffffffu, mx1, 2));

        float mn0 = fmaxf(m0, mx0), mn1 = fmaxf(m1, mx1);
        float al0 = __expf(m0 - mn0), al1 = __expf(m1 - mn1);
        m0 = mn0; m1 = mn1;

        float r0 = 0.f, r1 = 0.f;
#pragma unroll
        for (int nf = 0; nf < 8; nf++) {
            S[nf][0] = __expf(S[nf][0] - mn0);
            S[nf][1] = __expf(S[nf][1] - mn0);
            S[nf][2] = __expf(S[nf][2] - mn1);
            S[nf][3] = __expf(S[nf][3] - mn1);
            r0 += S[nf][0] + S[nf][1];
            r1 += S[nf][2] + S[nf][3];
        }
        r0 += __shfl_xor_sync(0xffffffffu, r0, 1);
        r0 += __shfl_xor_sync(0xffffffffu, r0, 2);
        r1 += __shfl_xor_sync(0xffffffffu, r1, 1);
        r1 += __shfl_xor_sync(0xffffffffu, r1, 2);
        l0 = l0 * al0 + r0;
        l1 = l1 * al1 + r1;
#pragma unroll
        for (int nf = 0; nf < 8; nf++) {
            O[nf][0] *= al0; O[nf][1] *= al0;
            O[nf][2] *= al1; O[nf][3] *= al1;
        }

        // P -> smem (warp-local rows; block barrier first: other warps may
        // still be reading this region as K)
        __syncthreads();
#pragma unroll
        for (int nf = 0; nf < 8; nf++) {
            int col = nf * 8 + 2 * c;
            KPs[(wq + g) * QST + col]     = S[nf][0];
            KPs[(wq + g) * QST + col + 1] = S[nf][1];
            KPs[(wq + g + 8) * QST + col]     = S[nf][2];
            KPs[(wq + g + 8) * QST + col + 1] = S[nf][3];
        }
        __syncwarp();

        // O += P @ V
#pragma unroll
        for (int ks = 0; ks < 8; ks++) {
            const int kb = ks * 8;
            unsigned a[4];
            int ab = (wq + g) * QST + kb + c;
            a[0] = f2tf(KPs[ab]);
            a[1] = f2tf(KPs[ab + 8 * QST]);
            a[2] = f2tf(KPs[ab + 4]);
            a[3] = f2tf(KPs[ab + 8 * QST + 4]);
#pragma unroll
            for (int nf = 0; nf < 8; nf++) {
                unsigned b0 = f2tf(Vs[(kb + c) * VST + nf * 8 + g]);
                unsigned b1 = f2tf(Vs[(kb + c + 4) * VST + nf * 8 + g]);
                mma8(O[nf], a, b0, b1);
            }
        }
    }

    // normalize + store [b, n, h*64 + d]
    float inv0 = 1.f / l0, inv1 = 1.f / l1;
#pragma unroll
    for (int nf = 0; nf < 8; nf++) {
        int d = nf * 8 + 2 * c;
        if (row0 < SEQ) {
            float2 o = make_float2(O[nf][0] * inv0, O[nf][1] * inv0);
            *(float2*)&op[(size_t)(b * SEQ + row0) * DIM + h * HD + d] = o;
        }
        if (row1 < SEQ) {
            float2 o = make_float2(O[nf][2] * inv1, O[nf][3] * inv1);
            *(float2*)&op[(size_t)(b * SEQ + row1) * DIM + h * HD + d] = o;
        }
    }
}

extern "C" void kernel_launch(void* const* d_in, const int* in_sizes, int n_in,
                              void* d_out, int out_size) {
    const float* x      = (const float*)d_in[0];
    const float* qkv_w  = (const float*)d_in[1];
    const float* qkv_b  = (const float*)d_in[2];
    const float* proj_w = (const float*)d_in[3];
    const float* proj_b = (const float*)d_in[4];
    float* out = (float*)d_out;

    float* qkvp = nullptr;
    float* attnp = nullptr;
    cudaGetSymbolAddress((void**)&qkvp, g_qkv);
    cudaGetSymbolAddress((void**)&attnp, g_attn);

    const int gemm_smem = 6 * SSZ * 4;                       // 61440
    const int attn_smem = (2 * 64 * QST + 64 * VST) * 4;     // 53248
    cudaFuncSetAttribute(gemm_tf32, cudaFuncAttributeMaxDynamicSharedMemorySize, gemm_smem);
    cudaFuncSetAttribute(attn_mma, cudaFuncAttributeMaxDynamicSharedMemorySize, attn_smem);

    dim3 g1(QKVC / 128, (MTOT + 127) / 128);
    gemm_tf32<<<g1, 256, gemm_smem>>>(x, qkv_w, qkv_b, qkvp, MTOT, QKVC, DIM);

    dim3 g2(6, BATCH * HEADS);
    attn_mma<<<g2, 128, attn_smem>>>(qkvp, attnp);

    dim3 g3(DIM / 128, (MTOT + 127) / 128);
    gemm_tf32<<<g3, 256, gemm_smem>>>(attnp, proj_w, proj_b, out, MTOT, DIM, DIM);
}